// round 10
// baseline (speedup 1.0000x reference)
#include <cuda_runtime.h>
#include <cuda_fp16.h>
#include <cstdint>

// ConditionalAffineCoupling — round 10: fp16 HMMA, 64x64 warp tiles
// (128 smem bytes/MMA vs 192), CTA 256x128, 1 CTA/SM with 256-reg budget.
// Coupling fused into GEMM2 (interleaved W2 cols), deterministic log_det.

#define B_TOT 131072
#define DIM   512
#define CTXD  128
#define HID   2048
#define KIN   384

// ------------------------- device scratch (allocation-free) ----------------
__device__ __align__(1024) __half g_a1 [(size_t)B_TOT * KIN];
__device__ __align__(1024) __half g_h  [(size_t)B_TOT * HID];
__device__ __align__(1024) __half g_w1t[(size_t)HID * KIN];
__device__ __align__(1024) __half g_w2t[(size_t)DIM * HID];   // interleaved cols
__device__ __align__(1024) float  g_b2i[DIM];                 // interleaved bias
__device__ __align__(1024) float  g_ldp[4][B_TOT];            // log_det partials

// ------------------------- helpers -----------------------------------------
__device__ __forceinline__ uint32_t smem_u32(const void* p) {
    uint32_t a;
    asm("{ .reg .u64 t; cvta.to.shared.u64 t, %1; cvt.u32.u64 %0, t; }"
        : "=r"(a) : "l"(p));
    return a;
}
__device__ __forceinline__ uint32_t swz128(uint32_t o) { return o ^ ((o >> 3) & 0x70); }

__device__ __forceinline__ void cp16(uint32_t sdst, const void* gsrc) {
    asm volatile("cp.async.cg.shared.global [%0], [%1], 16;"
                 :: "r"(sdst), "l"(gsrc));
}
__device__ __forceinline__ void ldsm4(uint32_t r[4], uint32_t addr) {
    asm volatile("ldmatrix.sync.aligned.m8n8.x4.shared.b16 {%0,%1,%2,%3}, [%4];"
                 : "=r"(r[0]), "=r"(r[1]), "=r"(r[2]), "=r"(r[3]) : "r"(addr));
}
__device__ __forceinline__ void mma16816(float c[4], const uint32_t a[4], const uint32_t b[2]) {
    asm volatile(
        "mma.sync.aligned.m16n8k16.row.col.f32.f16.f16.f32 "
        "{%0,%1,%2,%3}, {%4,%5,%6,%7}, {%8,%9}, {%0,%1,%2,%3};"
        : "+f"(c[0]), "+f"(c[1]), "+f"(c[2]), "+f"(c[3])
        : "r"(a[0]), "r"(a[1]), "r"(a[2]), "r"(a[3]), "r"(b[0]), "r"(b[1]));
}

// ------------------------- prep kernels ------------------------------------
__global__ void prep_w1t(const float* __restrict__ W1) {
    int i = blockIdx.x * 256 + threadIdx.x;
    if (i >= HID * KIN) return;
    int n = i / KIN, k = i % KIN;
    g_w1t[i] = __float2half(W1[(size_t)k * HID + n]);
}
// Interleave: new col 2j = old col j (s), new col 2j+1 = old col 256+j (t).
__global__ void prep_w2t(const float* __restrict__ W2, const float* __restrict__ b2) {
    int i = blockIdx.x * 256 + threadIdx.x;
    if (i < DIM) {
        int on = (i & 1) ? 256 + (i >> 1) : (i >> 1);
        g_b2i[i] = b2[on];
    }
    if (i >= DIM * HID) return;
    int n = i / HID, k = i % HID;
    int on = (n & 1) ? 256 + (n >> 1) : (n >> 1);
    g_w2t[i] = __float2half(W2[(size_t)k * DIM + on]);
}
__global__ void prep_a1(const float* __restrict__ x, const float* __restrict__ ctx) {
    size_t i = (size_t)blockIdx.x * 256 + threadIdx.x;
    if (i >= (size_t)B_TOT * KIN) return;
    int k = (int)(i % KIN);
    size_t row = i / KIN;
    float v = (k < 256) ? x[row * DIM + 2 * k] : ctx[row * CTXD + (k - 256)];
    g_a1[i] = __float2half(v);
}

// ------------------------- main GEMM (64x64 warp tiles) ---------------------
// MODE 0: A=g_a1 (K=384),  B=g_w1t (2048xK); epi: relu(+b1) -> g_h fp16
// MODE 1: A=g_h  (K=2048), B=g_w2t (512xK, interleaved); epi: fused coupling
// CTA 256x128 (M x N), BK=64 (128B rows, SW128), 3-stage cp.async.
// 8 warps: wm (0..3) x wn (0..1), each warp 64 rows x 64 cols.
// Stage smem: A 32KB | B 16KB = 48KB; x3 stages = 144KB. 1 CTA/SM.
template <int MODE>
__global__ __launch_bounds__(256, 1)
void gemm_mma(const float* __restrict__ bias_in,
              const float* __restrict__ x,
              float* __restrict__ out)
{
    constexpr int KTOT   = MODE ? HID : KIN;
    constexpr int C      = KTOT / 64;
    constexpr int PITCH  = KTOT * 2;        // bytes per row (A and B^T K-major)
    constexpr int STAGE  = 49152;
    constexpr int B_OFF  = 32768;

    const float* bias = MODE ? (const float*)g_b2i : bias_in;

    extern __shared__ char smem[];
    const uint32_t sb = smem_u32(smem);
    const int tid  = threadIdx.x, lane = tid & 31, wid = tid >> 5;
    const int wm   = wid >> 1;              // 0..3  (64-row slabs)
    const int wn   = wid & 1;               // 0..1  (64-col slabs)
    const int n0   = blockIdx.x * 128;
    const int bm0  = blockIdx.y * 256;

    const char* A = (const char*)(MODE ? g_h   : g_a1)  + (size_t)bm0 * PITCH;
    const char* B = (const char*)(MODE ? g_w2t : g_w1t) + (size_t)n0  * PITCH;

    // loader: A 256 rows x 8 chunks = 2048 cp16 (8/thread);
    //         B 128 rows x 8 chunks = 1024 cp16 (4/thread)
    const int lrow = tid >> 3, lchk = (tid & 7) * 16;

    auto load_stage = [&](int s) {
        const uint32_t base = sb + (s % 3) * STAGE;
        const size_t kb = (size_t)s * 128;
        #pragma unroll
        for (int i = 0; i < 8; ++i) {
            int r = lrow + i * 32;
            uint32_t so = swz128((uint32_t)(r * 128 + lchk));
            cp16(base + so, A + (size_t)r * PITCH + kb + lchk);
        }
        #pragma unroll
        for (int i = 0; i < 4; ++i) {
            int r = lrow + i * 32;
            uint32_t so = swz128((uint32_t)(r * 128 + lchk));
            cp16(base + B_OFF + so, B + (size_t)r * PITCH + kb + lchk);
        }
    };

    // ldmatrix lane address components
    const int a_row  = wm * 64 + (lane & 15);               // + mt*16
    const int a_byte = (lane >> 4) * 16;                    // + ksub*32
    const int b_l8   = lane & 7;
    const int b_grp  = lane >> 3;                           // 0..3
    const int b_row0 = wn * 64 + (b_grp >> 1) * 8 + b_l8;   // + p*16
    const int b_byte = (b_grp & 1) * 16;                    // + ksub*32

    float acc[4][8][4] = {};

    load_stage(0); asm volatile("cp.async.commit_group;" ::: "memory");
    load_stage(1); asm volatile("cp.async.commit_group;" ::: "memory");

    #pragma unroll 1
    for (int c = 0; c < C; ++c) {
        if (c < C - 1) asm volatile("cp.async.wait_group 1;" ::: "memory");
        else           asm volatile("cp.async.wait_group 0;" ::: "memory");
        __syncthreads();

        if (c + 2 < C) {
            load_stage(c + 2);
            asm volatile("cp.async.commit_group;" ::: "memory");
        }

        const uint32_t stb = sb + (c % 3) * STAGE;
        #pragma unroll
        for (int ksub = 0; ksub < 4; ++ksub) {
            // B fragments: 4x ldsm4 cover all 8 n-tiles for this k16
            uint32_t bf[8][2];
            #pragma unroll
            for (int p = 0; p < 4; ++p) {
                uint32_t r4[4];
                ldsm4(r4, stb + B_OFF +
                    swz128((uint32_t)((b_row0 + p * 16) * 128 + ksub * 32 + b_byte)));
                bf[2 * p][0] = r4[0]; bf[2 * p][1] = r4[1];
                bf[2 * p + 1][0] = r4[2]; bf[2 * p + 1][1] = r4[3];
            }
            #pragma unroll
            for (int mt = 0; mt < 4; ++mt) {
                uint32_t af[4];
                ldsm4(af, stb +
                    swz128((uint32_t)((a_row + mt * 16) * 128 + ksub * 32 + a_byte)));
                #pragma unroll
                for (int nt = 0; nt < 8; ++nt) mma16816(acc[mt][nt], af, bf[nt]);
            }
        }
    }

    // ------------------------- epilogue -------------------------------------
    const int q = lane >> 2;                         // row-in-8
    const int npair = (lane & 3) * 2;

    if constexpr (MODE == 0) {
        #pragma unroll
        for (int nt = 0; nt < 8; ++nt) {
            const int gn = n0 + wn * 64 + nt * 8 + npair;
            const float bv0 = __ldg(bias + gn), bv1 = __ldg(bias + gn + 1);
            #pragma unroll
            for (int mt = 0; mt < 4; ++mt) {
                const int r0 = bm0 + wm * 64 + mt * 16 + q;
                __half2 v0 = __floats2half2_rn(fmaxf(acc[mt][nt][0] + bv0, 0.f),
                                               fmaxf(acc[mt][nt][1] + bv1, 0.f));
                __half2 v1 = __floats2half2_rn(fmaxf(acc[mt][nt][2] + bv0, 0.f),
                                               fmaxf(acc[mt][nt][3] + bv1, 0.f));
                *(__half2*)(g_h + (size_t)r0 * HID + gn)       = v0;
                *(__half2*)(g_h + (size_t)(r0 + 8) * HID + gn) = v1;
            }
        }
    } else {
        // Fused coupling: acc pair (c0,c1) = (s_raw, t_raw) for column pair gn.
        float ldp[8] = {0.f, 0.f, 0.f, 0.f, 0.f, 0.f, 0.f, 0.f};
        #pragma unroll
        for (int nt = 0; nt < 8; ++nt) {
            const int gn = n0 + wn * 64 + nt * 8 + npair;
            const float bs = __ldg(bias + gn), bt = __ldg(bias + gn + 1);
            #pragma unroll
            for (int mt = 0; mt < 4; ++mt) {
                const int r0 = bm0 + wm * 64 + mt * 16 + q;
                #pragma unroll
                for (int hh = 0; hh < 2; ++hh) {
                    const int r = r0 + hh * 8;
                    float s_raw = acc[mt][nt][2 * hh]     + bs;
                    float t_val = acc[mt][nt][2 * hh + 1] + bt;
                    float e2 = __expf(2.f * s_raw);
                    float s  = 5.f * (1.f - 2.f / (e2 + 1.f));   // 5*tanh
                    ldp[mt * 2 + hh] += s;
                    float2 xv = *(const float2*)(x + (size_t)r * DIM + gn);
                    float2 o  = make_float2(xv.x, xv.y * __expf(s) + t_val);
                    *(float2*)(out + (size_t)r * DIM + gn) = o;
                }
            }
        }
        // quad reduce (lanes of a quad share the same rows)
        #pragma unroll
        for (int i = 0; i < 8; ++i) {
            ldp[i] += __shfl_xor_sync(0xffffffffu, ldp[i], 1);
            ldp[i] += __shfl_xor_sync(0xffffffffu, ldp[i], 2);
        }
        __syncthreads();                     // smem (stages) now reusable
        float* red = (float*)smem;           // [256 rows][2 wn]
        if ((lane & 3) == 0) {
            #pragma unroll
            for (int i = 0; i < 8; ++i) {
                int row_local = wm * 64 + (i >> 1) * 16 + q + (i & 1) * 8;
                red[row_local * 2 + wn] = ldp[i];
            }
        }
        __syncthreads();
        {
            float p = red[tid * 2] + red[tid * 2 + 1];
            g_ldp[blockIdx.x][bm0 + tid] = p;
        }
    }
}

// ------------------------- log_det final reduce -----------------------------
__global__ __launch_bounds__(256)
void ldred(float* __restrict__ out)
{
    int r = blockIdx.x * 256 + threadIdx.x;
    out[(size_t)B_TOT * DIM + r] =
        g_ldp[0][r] + g_ldp[1][r] + g_ldp[2][r] + g_ldp[3][r];
}

// ------------------------- launch ------------------------------------------
extern "C" void kernel_launch(void* const* d_in, const int* in_sizes, int n_in,
                              void* d_out, int out_size)
{
    const float* x   = (const float*)d_in[0];
    const float* ctx = (const float*)d_in[1];
    const float* W1  = (const float*)d_in[2];
    const float* b1  = (const float*)d_in[3];
    const float* W2  = (const float*)d_in[4];
    const float* b2  = (const float*)d_in[5];
    float* out = (float*)d_out;

    cudaFuncSetAttribute(gemm_mma<0>, cudaFuncAttributeMaxDynamicSharedMemorySize, 147456);
    cudaFuncSetAttribute(gemm_mma<1>, cudaFuncAttributeMaxDynamicSharedMemorySize, 147456);

    prep_w1t<<<(HID * KIN + 255) / 256, 256>>>(W1);
    prep_w2t<<<(DIM * HID + 255) / 256, 256>>>(W2, b2);
    prep_a1<<<(int)(((size_t)B_TOT * KIN + 255) / 256), 256>>>(x, ctx);

    gemm_mma<0><<<dim3(HID / 128, B_TOT / 256), 256, 147456>>>(b1, nullptr, nullptr);
    gemm_mma<1><<<dim3(DIM / 128, B_TOT / 256), 256, 147456>>>(nullptr, x, out);

    ldred<<<B_TOT / 256, 256>>>(out);
}

// round 11
// speedup vs baseline: 1.1482x; 1.1482x over previous
#include <cuda_runtime.h>
#include <cuda_fp16.h>
#include <cstdint>

// ConditionalAffineCoupling — round 11: fp16 HMMA, 64x64 warp tiles in a
// 4-warp (128-thread) 128x128 CTA, 2 CTAs/SM. Crossbar traffic/MMA cut 25%
// vs R8 while keeping cross-CTA overlap. Fused coupling epilogue in GEMM2.

#define B_TOT 131072
#define DIM   512
#define CTXD  128
#define HID   2048
#define KIN   384

// ------------------------- device scratch (allocation-free) ----------------
__device__ __align__(1024) __half g_a1 [(size_t)B_TOT * KIN];
__device__ __align__(1024) __half g_h  [(size_t)B_TOT * HID];
__device__ __align__(1024) __half g_w1t[(size_t)HID * KIN];
__device__ __align__(1024) __half g_w2t[(size_t)DIM * HID];   // interleaved cols
__device__ __align__(1024) float  g_b2i[DIM];                 // interleaved bias
__device__ __align__(1024) float  g_ldp[4][B_TOT];            // log_det partials

// ------------------------- helpers -----------------------------------------
__device__ __forceinline__ uint32_t smem_u32(const void* p) {
    uint32_t a;
    asm("{ .reg .u64 t; cvta.to.shared.u64 t, %1; cvt.u32.u64 %0, t; }"
        : "=r"(a) : "l"(p));
    return a;
}
__device__ __forceinline__ uint32_t swz128(uint32_t o) { return o ^ ((o >> 3) & 0x70); }

__device__ __forceinline__ void cp16(uint32_t sdst, const void* gsrc) {
    asm volatile("cp.async.cg.shared.global [%0], [%1], 16;"
                 :: "r"(sdst), "l"(gsrc));
}
__device__ __forceinline__ void ldsm4(uint32_t r[4], uint32_t addr) {
    asm volatile("ldmatrix.sync.aligned.m8n8.x4.shared.b16 {%0,%1,%2,%3}, [%4];"
                 : "=r"(r[0]), "=r"(r[1]), "=r"(r[2]), "=r"(r[3]) : "r"(addr));
}
__device__ __forceinline__ void mma16816(float c[4], const uint32_t a[4], const uint32_t b[2]) {
    asm volatile(
        "mma.sync.aligned.m16n8k16.row.col.f32.f16.f16.f32 "
        "{%0,%1,%2,%3}, {%4,%5,%6,%7}, {%8,%9}, {%0,%1,%2,%3};"
        : "+f"(c[0]), "+f"(c[1]), "+f"(c[2]), "+f"(c[3])
        : "r"(a[0]), "r"(a[1]), "r"(a[2]), "r"(a[3]), "r"(b[0]), "r"(b[1]));
}

// ------------------------- prep kernels ------------------------------------
__global__ void prep_w1t(const float* __restrict__ W1) {
    int i = blockIdx.x * 256 + threadIdx.x;
    if (i >= HID * KIN) return;
    int n = i / KIN, k = i % KIN;
    g_w1t[i] = __float2half(W1[(size_t)k * HID + n]);
}
// Interleave: new col 2j = old col j (s), new col 2j+1 = old col 256+j (t).
__global__ void prep_w2t(const float* __restrict__ W2, const float* __restrict__ b2) {
    int i = blockIdx.x * 256 + threadIdx.x;
    if (i < DIM) {
        int on = (i & 1) ? 256 + (i >> 1) : (i >> 1);
        g_b2i[i] = b2[on];
    }
    if (i >= DIM * HID) return;
    int n = i / HID, k = i % HID;
    int on = (n & 1) ? 256 + (n >> 1) : (n >> 1);
    g_w2t[i] = __float2half(W2[(size_t)k * DIM + on]);
}
__global__ void prep_a1(const float* __restrict__ x, const float* __restrict__ ctx) {
    size_t i = (size_t)blockIdx.x * 256 + threadIdx.x;
    if (i >= (size_t)B_TOT * KIN) return;
    int k = (int)(i % KIN);
    size_t row = i / KIN;
    float v = (k < 256) ? x[row * DIM + 2 * k] : ctx[row * CTXD + (k - 256)];
    g_a1[i] = __float2half(v);
}

// ------------------------- main GEMM (4 warps, 64x64 tiles) -----------------
// MODE 0: A=g_a1 (K=384),  B=g_w1t (2048xK); epi: relu(+b1) -> g_h fp16
// MODE 1: A=g_h  (K=2048), B=g_w2t (512xK, interleaved); epi: fused coupling
// CTA 128x128, BK=64 (128B rows, SW128), 3-stage cp.async, 128 threads.
// Warp grid 2x2 (wm, wn), each warp 64x64. Stage: A 16KB | B 16KB; x3 = 96KB.
template <int MODE>
__global__ __launch_bounds__(128, 2)
void gemm_mma(const float* __restrict__ bias_in,
              const float* __restrict__ x,
              float* __restrict__ out)
{
    constexpr int KTOT   = MODE ? HID : KIN;
    constexpr int C      = KTOT / 64;
    constexpr int PITCH  = KTOT * 2;        // bytes per row (A and B^T K-major)
    constexpr int STAGE  = 32768;
    constexpr int B_OFF  = 16384;

    const float* bias = MODE ? (const float*)g_b2i : bias_in;

    extern __shared__ char smem[];
    const uint32_t sb = smem_u32(smem);
    const int tid  = threadIdx.x, lane = tid & 31, wid = tid >> 5;
    const int wm   = wid >> 1;              // 0..1  (64-row slabs)
    const int wn   = wid & 1;               // 0..1  (64-col slabs)
    const int n0   = blockIdx.x * 128;
    const int bm0  = blockIdx.y * 128;

    const char* A = (const char*)(MODE ? g_h   : g_a1)  + (size_t)bm0 * PITCH;
    const char* B = (const char*)(MODE ? g_w2t : g_w1t) + (size_t)n0  * PITCH;

    // loader: each region 128 rows x 8 chunks(16B) = 1024 cp16; 8/thread/region
    const int lrow = tid >> 3, lchk = (tid & 7) * 16;

    auto load_stage = [&](int s) {
        const uint32_t base = sb + (s % 3) * STAGE;
        const size_t kb = (size_t)s * 128;
        #pragma unroll
        for (int i = 0; i < 8; ++i) {
            int r = lrow + i * 16;
            uint32_t so = swz128((uint32_t)(r * 128 + lchk));
            size_t go = (size_t)r * PITCH + kb + lchk;
            cp16(base + so,         A + go);
            cp16(base + B_OFF + so, B + go);
        }
    };

    // ldmatrix lane address components
    const int a_row  = wm * 64 + (lane & 15);               // + mt*16
    const int a_byte = (lane >> 4) * 16;                    // + ksub*32
    const int b_l8   = lane & 7;
    const int b_grp  = lane >> 3;                           // 0..3
    const int b_row0 = wn * 64 + (b_grp >> 1) * 8 + b_l8;   // + p*16
    const int b_byte = (b_grp & 1) * 16;                    // + ksub*32

    float acc[4][8][4] = {};

    load_stage(0); asm volatile("cp.async.commit_group;" ::: "memory");
    load_stage(1); asm volatile("cp.async.commit_group;" ::: "memory");

    #pragma unroll 1
    for (int c = 0; c < C; ++c) {
        if (c < C - 1) asm volatile("cp.async.wait_group 1;" ::: "memory");
        else           asm volatile("cp.async.wait_group 0;" ::: "memory");
        __syncthreads();

        if (c + 2 < C) {
            load_stage(c + 2);
            asm volatile("cp.async.commit_group;" ::: "memory");
        }

        const uint32_t stb = sb + (c % 3) * STAGE;
        #pragma unroll
        for (int ksub = 0; ksub < 4; ++ksub) {
            // B fragments: 4x ldsm4 cover all 8 n-tiles for this k16
            uint32_t bf[8][2];
            #pragma unroll
            for (int p = 0; p < 4; ++p) {
                uint32_t r4[4];
                ldsm4(r4, stb + B_OFF +
                    swz128((uint32_t)((b_row0 + p * 16) * 128 + ksub * 32 + b_byte)));
                bf[2 * p][0] = r4[0]; bf[2 * p][1] = r4[1];
                bf[2 * p + 1][0] = r4[2]; bf[2 * p + 1][1] = r4[3];
            }
            #pragma unroll
            for (int mt = 0; mt < 4; ++mt) {
                uint32_t af[4];
                ldsm4(af, stb +
                    swz128((uint32_t)((a_row + mt * 16) * 128 + ksub * 32 + a_byte)));
                #pragma unroll
                for (int nt = 0; nt < 8; ++nt) mma16816(acc[mt][nt], af, bf[nt]);
            }
        }
    }

    // ------------------------- epilogue -------------------------------------
    const int q = lane >> 2;                         // row-in-8
    const int npair = (lane & 3) * 2;

    if constexpr (MODE == 0) {
        #pragma unroll
        for (int nt = 0; nt < 8; ++nt) {
            const int gn = n0 + wn * 64 + nt * 8 + npair;
            const float bv0 = __ldg(bias + gn), bv1 = __ldg(bias + gn + 1);
            #pragma unroll
            for (int mt = 0; mt < 4; ++mt) {
                const int r0 = bm0 + wm * 64 + mt * 16 + q;
                __half2 v0 = __floats2half2_rn(fmaxf(acc[mt][nt][0] + bv0, 0.f),
                                               fmaxf(acc[mt][nt][1] + bv1, 0.f));
                __half2 v1 = __floats2half2_rn(fmaxf(acc[mt][nt][2] + bv0, 0.f),
                                               fmaxf(acc[mt][nt][3] + bv1, 0.f));
                *(__half2*)(g_h + (size_t)r0 * HID + gn)       = v0;
                *(__half2*)(g_h + (size_t)(r0 + 8) * HID + gn) = v1;
            }
        }
    } else {
        // Fused coupling: acc pair (c0,c1) = (s_raw, t_raw) for column pair gn.
        float ldp[8] = {0.f, 0.f, 0.f, 0.f, 0.f, 0.f, 0.f, 0.f};
        #pragma unroll
        for (int nt = 0; nt < 8; ++nt) {
            const int gn = n0 + wn * 64 + nt * 8 + npair;
            const float bs = __ldg(bias + gn), bt = __ldg(bias + gn + 1);
            #pragma unroll
            for (int mt = 0; mt < 4; ++mt) {
                const int r0 = bm0 + wm * 64 + mt * 16 + q;
                #pragma unroll
                for (int hh = 0; hh < 2; ++hh) {
                    const int r = r0 + hh * 8;
                    float s_raw = acc[mt][nt][2 * hh]     + bs;
                    float t_val = acc[mt][nt][2 * hh + 1] + bt;
                    float e2 = __expf(2.f * s_raw);
                    float s  = 5.f * (1.f - 2.f / (e2 + 1.f));   // 5*tanh
                    ldp[mt * 2 + hh] += s;
                    float2 xv = *(const float2*)(x + (size_t)r * DIM + gn);
                    float2 o  = make_float2(xv.x, xv.y * __expf(s) + t_val);
                    *(float2*)(out + (size_t)r * DIM + gn) = o;
                }
            }
        }
        // quad reduce (lanes of a quad share the same rows)
        #pragma unroll
        for (int i = 0; i < 8; ++i) {
            ldp[i] += __shfl_xor_sync(0xffffffffu, ldp[i], 1);
            ldp[i] += __shfl_xor_sync(0xffffffffu, ldp[i], 2);
        }
        __syncthreads();                     // smem (stages) now reusable
        float* red = (float*)smem;           // [128 rows][2 wn]
        if ((lane & 3) == 0) {
            #pragma unroll
            for (int i = 0; i < 8; ++i) {
                int row_local = wm * 64 + (i >> 1) * 16 + q + (i & 1) * 8;
                red[row_local * 2 + wn] = ldp[i];
            }
        }
        __syncthreads();
        {
            float p = red[tid * 2] + red[tid * 2 + 1];
            g_ldp[blockIdx.x][bm0 + tid] = p;
        }
    }
}

// ------------------------- log_det final reduce -----------------------------
__global__ __launch_bounds__(256)
void ldred(float* __restrict__ out)
{
    int r = blockIdx.x * 256 + threadIdx.x;
    out[(size_t)B_TOT * DIM + r] =
        g_ldp[0][r] + g_ldp[1][r] + g_ldp[2][r] + g_ldp[3][r];
}

// ------------------------- launch ------------------------------------------
extern "C" void kernel_launch(void* const* d_in, const int* in_sizes, int n_in,
                              void* d_out, int out_size)
{
    const float* x   = (const float*)d_in[0];
    const float* ctx = (const float*)d_in[1];
    const float* W1  = (const float*)d_in[2];
    const float* b1  = (const float*)d_in[3];
    const float* W2  = (const float*)d_in[4];
    const float* b2  = (const float*)d_in[5];
    float* out = (float*)d_out;

    cudaFuncSetAttribute(gemm_mma<0>, cudaFuncAttributeMaxDynamicSharedMemorySize, 98304);
    cudaFuncSetAttribute(gemm_mma<1>, cudaFuncAttributeMaxDynamicSharedMemorySize, 98304);

    prep_w1t<<<(HID * KIN + 255) / 256, 256>>>(W1);
    prep_w2t<<<(DIM * HID + 255) / 256, 256>>>(W2, b2);
    prep_a1<<<(int)(((size_t)B_TOT * KIN + 255) / 256), 256>>>(x, ctx);

    gemm_mma<0><<<dim3(HID / 128, B_TOT / 128), 128, 98304>>>(b1, nullptr, nullptr);
    gemm_mma<1><<<dim3(DIM / 128, B_TOT / 128), 128, 98304>>>(nullptr, x, out);

    ldred<<<B_TOT / 256, 256>>>(out);
}

// round 12
// speedup vs baseline: 1.2788x; 1.1138x over previous
#include <cuda_runtime.h>
#include <cuda_fp16.h>
#include <cstdint>

// ConditionalAffineCoupling — round 12: hybrid of measured winners.
// gemm1: 128-thread CTA, 2x2 warps of 64x64 (R11 config, 535us).
// gemm2: 256-thread CTA, 2x4 warps of 64x32 + fused coupling (R8 config).

#define B_TOT 131072
#define DIM   512
#define CTXD  128
#define HID   2048
#define KIN   384

// ------------------------- device scratch (allocation-free) ----------------
__device__ __align__(1024) __half g_a1 [(size_t)B_TOT * KIN];
__device__ __align__(1024) __half g_h  [(size_t)B_TOT * HID];
__device__ __align__(1024) __half g_w1t[(size_t)HID * KIN];
__device__ __align__(1024) __half g_w2t[(size_t)DIM * HID];   // interleaved cols
__device__ __align__(1024) float  g_b2i[DIM];                 // interleaved bias
__device__ __align__(1024) float  g_ldp[4][B_TOT];            // log_det partials

// ------------------------- helpers -----------------------------------------
__device__ __forceinline__ uint32_t smem_u32(const void* p) {
    uint32_t a;
    asm("{ .reg .u64 t; cvta.to.shared.u64 t, %1; cvt.u32.u64 %0, t; }"
        : "=r"(a) : "l"(p));
    return a;
}
__device__ __forceinline__ uint32_t swz128(uint32_t o) { return o ^ ((o >> 3) & 0x70); }

__device__ __forceinline__ void cp16(uint32_t sdst, const void* gsrc) {
    asm volatile("cp.async.cg.shared.global [%0], [%1], 16;"
                 :: "r"(sdst), "l"(gsrc));
}
__device__ __forceinline__ void ldsm4(uint32_t r[4], uint32_t addr) {
    asm volatile("ldmatrix.sync.aligned.m8n8.x4.shared.b16 {%0,%1,%2,%3}, [%4];"
                 : "=r"(r[0]), "=r"(r[1]), "=r"(r[2]), "=r"(r[3]) : "r"(addr));
}
__device__ __forceinline__ void mma16816(float c[4], const uint32_t a[4], const uint32_t b[2]) {
    asm volatile(
        "mma.sync.aligned.m16n8k16.row.col.f32.f16.f16.f32 "
        "{%0,%1,%2,%3}, {%4,%5,%6,%7}, {%8,%9}, {%0,%1,%2,%3};"
        : "+f"(c[0]), "+f"(c[1]), "+f"(c[2]), "+f"(c[3])
        : "r"(a[0]), "r"(a[1]), "r"(a[2]), "r"(a[3]), "r"(b[0]), "r"(b[1]));
}

// ------------------------- prep kernels ------------------------------------
__global__ void prep_w1t(const float* __restrict__ W1) {
    int i = blockIdx.x * 256 + threadIdx.x;
    if (i >= HID * KIN) return;
    int n = i / KIN, k = i % KIN;
    g_w1t[i] = __float2half(W1[(size_t)k * HID + n]);
}
// Interleave: new col 2j = old col j (s), new col 2j+1 = old col 256+j (t).
__global__ void prep_w2t(const float* __restrict__ W2, const float* __restrict__ b2) {
    int i = blockIdx.x * 256 + threadIdx.x;
    if (i < DIM) {
        int on = (i & 1) ? 256 + (i >> 1) : (i >> 1);
        g_b2i[i] = b2[on];
    }
    if (i >= DIM * HID) return;
    int n = i / HID, k = i % HID;
    int on = (n & 1) ? 256 + (n >> 1) : (n >> 1);
    g_w2t[i] = __float2half(W2[(size_t)k * DIM + on]);
}
__global__ void prep_a1(const float* __restrict__ x, const float* __restrict__ ctx) {
    size_t i = (size_t)blockIdx.x * 256 + threadIdx.x;
    if (i >= (size_t)B_TOT * KIN) return;
    int k = (int)(i % KIN);
    size_t row = i / KIN;
    float v = (k < 256) ? x[row * DIM + 2 * k] : ctx[row * CTXD + (k - 256)];
    g_a1[i] = __float2half(v);
}

// ------------------------- GEMM1: h = relu(a1 @ W1^T + b1) ------------------
// CTA 128x128, BK=64, 3-stage cp.async, 128 threads (2x2 warps of 64x64).
// Stage: A 16KB | B 16KB = 32KB; x3 = 96KB. 2 CTAs/SM (regs ~232).
__global__ __launch_bounds__(128, 2)
void gemm1_k(const float* __restrict__ bias)
{
    constexpr int KTOT   = KIN;
    constexpr int C      = KTOT / 64;
    constexpr int PITCH  = KTOT * 2;
    constexpr int STAGE  = 32768;
    constexpr int B_OFF  = 16384;

    extern __shared__ char smem[];
    const uint32_t sb = smem_u32(smem);
    const int tid  = threadIdx.x, lane = tid & 31, wid = tid >> 5;
    const int wm   = wid >> 1;              // 0..1
    const int wn   = wid & 1;               // 0..1
    const int n0   = blockIdx.x * 128;
    const int bm0  = blockIdx.y * 128;

    const char* A = (const char*)g_a1  + (size_t)bm0 * PITCH;
    const char* B = (const char*)g_w1t + (size_t)n0  * PITCH;

    const int lrow = tid >> 3, lchk = (tid & 7) * 16;

    auto load_stage = [&](int s) {
        const uint32_t base = sb + (s % 3) * STAGE;
        const size_t kb = (size_t)s * 128;
        #pragma unroll
        for (int i = 0; i < 8; ++i) {
            int r = lrow + i * 16;
            uint32_t so = swz128((uint32_t)(r * 128 + lchk));
            size_t go = (size_t)r * PITCH + kb + lchk;
            cp16(base + so,         A + go);
            cp16(base + B_OFF + so, B + go);
        }
    };

    const int a_row  = wm * 64 + (lane & 15);
    const int a_byte = (lane >> 4) * 16;
    const int b_l8   = lane & 7;
    const int b_grp  = lane >> 3;
    const int b_row0 = wn * 64 + (b_grp >> 1) * 8 + b_l8;
    const int b_byte = (b_grp & 1) * 16;

    float acc[4][8][4] = {};

    load_stage(0); asm volatile("cp.async.commit_group;" ::: "memory");
    load_stage(1); asm volatile("cp.async.commit_group;" ::: "memory");

    #pragma unroll 1
    for (int c = 0; c < C; ++c) {
        if (c < C - 1) asm volatile("cp.async.wait_group 1;" ::: "memory");
        else           asm volatile("cp.async.wait_group 0;" ::: "memory");
        __syncthreads();

        if (c + 2 < C) {
            load_stage(c + 2);
            asm volatile("cp.async.commit_group;" ::: "memory");
        }

        const uint32_t stb = sb + (c % 3) * STAGE;
        #pragma unroll
        for (int ksub = 0; ksub < 4; ++ksub) {
            uint32_t bf[8][2];
            #pragma unroll
            for (int p = 0; p < 4; ++p) {
                uint32_t r4[4];
                ldsm4(r4, stb + B_OFF +
                    swz128((uint32_t)((b_row0 + p * 16) * 128 + ksub * 32 + b_byte)));
                bf[2 * p][0] = r4[0]; bf[2 * p][1] = r4[1];
                bf[2 * p + 1][0] = r4[2]; bf[2 * p + 1][1] = r4[3];
            }
            #pragma unroll
            for (int mt = 0; mt < 4; ++mt) {
                uint32_t af[4];
                ldsm4(af, stb +
                    swz128((uint32_t)((a_row + mt * 16) * 128 + ksub * 32 + a_byte)));
                #pragma unroll
                for (int nt = 0; nt < 8; ++nt) mma16816(acc[mt][nt], af, bf[nt]);
            }
        }
    }

    const int q = lane >> 2;
    const int npair = (lane & 3) * 2;
    #pragma unroll
    for (int nt = 0; nt < 8; ++nt) {
        const int gn = n0 + wn * 64 + nt * 8 + npair;
        const float bv0 = __ldg(bias + gn), bv1 = __ldg(bias + gn + 1);
        #pragma unroll
        for (int mt = 0; mt < 4; ++mt) {
            const int r0 = bm0 + wm * 64 + mt * 16 + q;
            __half2 v0 = __floats2half2_rn(fmaxf(acc[mt][nt][0] + bv0, 0.f),
                                           fmaxf(acc[mt][nt][1] + bv1, 0.f));
            __half2 v1 = __floats2half2_rn(fmaxf(acc[mt][nt][2] + bv0, 0.f),
                                           fmaxf(acc[mt][nt][3] + bv1, 0.f));
            *(__half2*)(g_h + (size_t)r0 * HID + gn)       = v0;
            *(__half2*)(g_h + (size_t)(r0 + 8) * HID + gn) = v1;
        }
    }
}

// ------------------------- GEMM2 + fused coupling ---------------------------
// CTA 128x128, BK=64, 3-stage cp.async, 256 threads (2x4 warps of 64x32).
// Stage: A 16KB | B 16KB = 32KB; x3 = 96KB. 2 CTAs/SM (regs ~124).
__global__ __launch_bounds__(256, 2)
void gemm2_k(const float* __restrict__ x, float* __restrict__ out)
{
    constexpr int KTOT   = HID;
    constexpr int C      = KTOT / 64;
    constexpr int PITCH  = KTOT * 2;
    constexpr int STAGE  = 32768;
    constexpr int B_OFF  = 16384;

    const float* bias = (const float*)g_b2i;

    extern __shared__ char smem[];
    const uint32_t sb = smem_u32(smem);
    const int tid  = threadIdx.x, lane = tid & 31, wid = tid >> 5;
    const int wm   = wid >> 2;              // 0..1
    const int wn   = wid & 3;               // 0..3
    const int n0   = blockIdx.x * 128;
    const int bm0  = blockIdx.y * 128;

    const char* A = (const char*)g_h   + (size_t)bm0 * PITCH;
    const char* B = (const char*)g_w2t + (size_t)n0  * PITCH;

    const int lrow = tid >> 3, lchk = (tid & 7) * 16;

    auto load_stage = [&](int s) {
        const uint32_t base = sb + (s % 3) * STAGE;
        const size_t kb = (size_t)s * 128;
        #pragma unroll
        for (int i = 0; i < 4; ++i) {
            int r = lrow + i * 32;
            uint32_t so = swz128((uint32_t)(r * 128 + lchk));
            size_t go = (size_t)r * PITCH + kb + lchk;
            cp16(base + so,         A + go);
            cp16(base + B_OFF + so, B + go);
        }
    };

    const int a_row  = wm * 64 + (lane & 15);
    const int a_byte = (lane >> 4) * 16;
    const int b_l8   = lane & 7;
    const int b_grp  = lane >> 3;
    const int b_row0 = wn * 32 + (b_grp >> 1) * 8 + b_l8;
    const int b_byte = (b_grp & 1) * 16;

    float acc[4][4][4] = {};

    load_stage(0); asm volatile("cp.async.commit_group;" ::: "memory");
    load_stage(1); asm volatile("cp.async.commit_group;" ::: "memory");

    #pragma unroll 1
    for (int c = 0; c < C; ++c) {
        if (c < C - 1) asm volatile("cp.async.wait_group 1;" ::: "memory");
        else           asm volatile("cp.async.wait_group 0;" ::: "memory");
        __syncthreads();

        if (c + 2 < C) {
            load_stage(c + 2);
            asm volatile("cp.async.commit_group;" ::: "memory");
        }

        const uint32_t stb = sb + (c % 3) * STAGE;
        #pragma unroll
        for (int ksub = 0; ksub < 4; ++ksub) {
            uint32_t bf[4][2];
            #pragma unroll
            for (int p = 0; p < 2; ++p) {
                uint32_t r4[4];
                ldsm4(r4, stb + B_OFF +
                    swz128((uint32_t)((b_row0 + p * 16) * 128 + ksub * 32 + b_byte)));
                bf[2 * p][0] = r4[0]; bf[2 * p][1] = r4[1];
                bf[2 * p + 1][0] = r4[2]; bf[2 * p + 1][1] = r4[3];
            }
            #pragma unroll
            for (int mt = 0; mt < 4; ++mt) {
                uint32_t af[4];
                ldsm4(af, stb +
                    swz128((uint32_t)((a_row + mt * 16) * 128 + ksub * 32 + a_byte)));
                #pragma unroll
                for (int nt = 0; nt < 4; ++nt) mma16816(acc[mt][nt], af, bf[nt]);
            }
        }
    }

    // Fused coupling epilogue: acc pair (c0,c1) = (s_raw, t_raw).
    const int q = lane >> 2;
    const int npair = (lane & 3) * 2;
    float ldp[8] = {0.f, 0.f, 0.f, 0.f, 0.f, 0.f, 0.f, 0.f};
    #pragma unroll
    for (int nt = 0; nt < 4; ++nt) {
        const int gn = n0 + wn * 32 + nt * 8 + npair;
        const float bs = __ldg(bias + gn), bt = __ldg(bias + gn + 1);
        #pragma unroll
        for (int mt = 0; mt < 4; ++mt) {
            const int r0 = bm0 + wm * 64 + mt * 16 + q;
            #pragma unroll
            for (int hh = 0; hh < 2; ++hh) {
                const int r = r0 + hh * 8;
                float s_raw = acc[mt][nt][2 * hh]     + bs;
                float t_val = acc[mt][nt][2 * hh + 1] + bt;
                float e2 = __expf(2.f * s_raw);
                float s  = 5.f * (1.f - 2.f / (e2 + 1.f));   // 5*tanh
                ldp[mt * 2 + hh] += s;
                float2 xv = *(const float2*)(x + (size_t)r * DIM + gn);
                float2 o  = make_float2(xv.x, xv.y * __expf(s) + t_val);
                *(float2*)(out + (size_t)r * DIM + gn) = o;
            }
        }
    }
    #pragma unroll
    for (int i = 0; i < 8; ++i) {
        ldp[i] += __shfl_xor_sync(0xffffffffu, ldp[i], 1);
        ldp[i] += __shfl_xor_sync(0xffffffffu, ldp[i], 2);
    }
    __syncthreads();
    float* red = (float*)smem;           // [128 rows][4 wn]
    if ((lane & 3) == 0) {
        #pragma unroll
        for (int i = 0; i < 8; ++i) {
            int row_local = wm * 64 + (i >> 1) * 16 + q + (i & 1) * 8;
            red[row_local * 4 + wn] = ldp[i];
        }
    }
    __syncthreads();
    if (tid < 128) {
        float p = red[tid * 4] + red[tid * 4 + 1] +
                  red[tid * 4 + 2] + red[tid * 4 + 3];
        g_ldp[blockIdx.x][bm0 + tid] = p;
    }
}

// ------------------------- log_det final reduce -----------------------------
__global__ __launch_bounds__(256)
void ldred(float* __restrict__ out)
{
    int r = blockIdx.x * 256 + threadIdx.x;
    out[(size_t)B_TOT * DIM + r] =
        g_ldp[0][r] + g_ldp[1][r] + g_ldp[2][r] + g_ldp[3][r];
}

// ------------------------- launch ------------------------------------------
extern "C" void kernel_launch(void* const* d_in, const int* in_sizes, int n_in,
                              void* d_out, int out_size)
{
    const float* x   = (const float*)d_in[0];
    const float* ctx = (const float*)d_in[1];
    const float* W1  = (const float*)d_in[2];
    const float* b1  = (const float*)d_in[3];
    const float* W2  = (const float*)d_in[4];
    const float* b2  = (const float*)d_in[5];
    float* out = (float*)d_out;

    cudaFuncSetAttribute(gemm1_k, cudaFuncAttributeMaxDynamicSharedMemorySize, 98304);
    cudaFuncSetAttribute(gemm2_k, cudaFuncAttributeMaxDynamicSharedMemorySize, 98304);

    prep_w1t<<<(HID * KIN + 255) / 256, 256>>>(W1);
    prep_w2t<<<(DIM * HID + 255) / 256, 256>>>(W2, b2);
    prep_a1<<<(int)(((size_t)B_TOT * KIN + 255) / 256), 256>>>(x, ctx);

    gemm1_k<<<dim3(HID / 128, B_TOT / 128), 128, 98304>>>(b1);
    gemm2_k<<<dim3(DIM / 128, B_TOT / 128), 256, 98304>>>(x, out);

    ldred<<<B_TOT / 256, 256>>>(out);
}